// round 5
// baseline (speedup 1.0000x reference)
#include <cuda_runtime.h>
#include <cuda_bf16.h>
#include <cstdint>

// Problem constants (fixed by setup_inputs)
#define Bc   4
#define Lc   11253
#define ROWS (Bc * Lc)        // 45012
#define DMc  256
#define Mh   8
#define DHc  32
#define LVc  4
#define Pc   4
#define DFc  1024

// Hardcoded level geometry (SHAPES / level_start_index are problem constants;
// avoids depending on the harness's int64 materialization entirely).
__device__ __constant__ int c_H [4] = {92, 46, 23, 12};
__device__ __constant__ int c_W [4] = {92, 46, 23, 12};
__device__ __constant__ int c_S0[4] = {0, 8464, 10580, 11109};

// ---------------------------------------------------------------------------
// Scratch (allocation-free: __device__ globals), aliased across stages:
//   buf0: query -> samp ; buf1: value -> h ; buf2: off -> attn -> ffn2
// ---------------------------------------------------------------------------
__device__ float g_buf0 [ROWS * DMc];
__device__ float g_buf1 [ROWS * DMc];
__device__ float g_buf2 [ROWS * DMc];
__device__ float g_logit[ROWS * 128];
__device__ float g_ffn1 [ROWS * DFc];

// ---------------------------------------------------------------------------
// Elementwise add: query = q_feat + q_pos
// ---------------------------------------------------------------------------
__global__ void __launch_bounds__(256) add_kernel(
    const float* __restrict__ a, const float* __restrict__ b,
    float* __restrict__ o)
{
    size_t i = (size_t)blockIdx.x * 256 + threadIdx.x;
    o[i] = a[i] + b[i];
}

// ---------------------------------------------------------------------------
// SGEMM: C[Mr,N] = A[Mr,K] @ B[K,N] + bias (optional ReLU)
// BM=BN=128, BK=8, 256 threads, 8x8 per thread in 2x2 quadrants of 4x4.
// ---------------------------------------------------------------------------
template<bool RELU>
__global__ void __launch_bounds__(256) sgemm_bias(
    const float* __restrict__ A, const float* __restrict__ Bm,
    const float* __restrict__ bias, float* __restrict__ C,
    int Mr, int N, int K)
{
    __shared__ float As[8][128];
    __shared__ float Bs[8][128];

    const int tid  = threadIdx.x;
    const int row0 = blockIdx.x * 128;
    const int col0 = blockIdx.y * 128;

    const int tr = (tid >> 4) * 4;
    const int tc = (tid & 15) * 4;

    float acc[2][2][4][4];
    #pragma unroll
    for (int qi = 0; qi < 2; qi++)
        #pragma unroll
        for (int qj = 0; qj < 2; qj++)
            #pragma unroll
            for (int i = 0; i < 4; i++)
                #pragma unroll
                for (int j = 0; j < 4; j++)
                    acc[qi][qj][i][j] = 0.f;

    const int aRow = tid >> 1;
    const int aK   = (tid & 1) * 4;
    const int bRow = tid >> 5;
    const int bCol = (tid & 31) * 4;

    const bool aValid = (row0 + aRow) < Mr;
    const float* Aptr = A + (size_t)(row0 + aRow) * K + aK;
    const float* Bptr = Bm + (size_t)bRow * N + col0 + bCol;

    for (int k0 = 0; k0 < K; k0 += 8) {
        float4 av = aValid ? *(const float4*)(Aptr + k0)
                           : make_float4(0.f, 0.f, 0.f, 0.f);
        As[aK + 0][aRow] = av.x;
        As[aK + 1][aRow] = av.y;
        As[aK + 2][aRow] = av.z;
        As[aK + 3][aRow] = av.w;
        *(float4*)&Bs[bRow][bCol] = *(const float4*)(Bptr + (size_t)k0 * N);
        __syncthreads();

        #pragma unroll
        for (int kk = 0; kk < 8; kk++) {
            float4 a0 = *(const float4*)&As[kk][tr];
            float4 a1 = *(const float4*)&As[kk][tr + 64];
            float4 b0 = *(const float4*)&Bs[kk][tc];
            float4 b1 = *(const float4*)&Bs[kk][tc + 64];
            float ar[2][4] = {{a0.x, a0.y, a0.z, a0.w}, {a1.x, a1.y, a1.z, a1.w}};
            float br[2][4] = {{b0.x, b0.y, b0.z, b0.w}, {b1.x, b1.y, b1.z, b1.w}};
            #pragma unroll
            for (int qi = 0; qi < 2; qi++)
                #pragma unroll
                for (int qj = 0; qj < 2; qj++)
                    #pragma unroll
                    for (int i = 0; i < 4; i++)
                        #pragma unroll
                        for (int j = 0; j < 4; j++)
                            acc[qi][qj][i][j] += ar[qi][i] * br[qj][j];
        }
        __syncthreads();
    }

    #pragma unroll
    for (int qi = 0; qi < 2; qi++) {
        #pragma unroll
        for (int i = 0; i < 4; i++) {
            int gr = row0 + tr + qi * 64 + i;
            if (gr >= Mr) continue;
            #pragma unroll
            for (int qj = 0; qj < 2; qj++) {
                int gc = col0 + tc + qj * 64;
                float4 bv = *(const float4*)&bias[gc];
                float4 o;
                o.x = acc[qi][qj][i][0] + bv.x;
                o.y = acc[qi][qj][i][1] + bv.y;
                o.z = acc[qi][qj][i][2] + bv.z;
                o.w = acc[qi][qj][i][3] + bv.w;
                if (RELU) {
                    o.x = fmaxf(o.x, 0.f); o.y = fmaxf(o.y, 0.f);
                    o.z = fmaxf(o.z, 0.f); o.w = fmaxf(o.w, 0.f);
                }
                *(float4*)&C[(size_t)gr * N + gc] = o;
            }
        }
    }
}

// ---------------------------------------------------------------------------
// Deformable sampling: 1 block per query row, 1 warp per head, lane = channel.
// Softmax over LV*P=16 logits per head, then bilinear gather-accumulate.
// Level geometry is compile-time constant (c_H/c_W/c_S0).
// ---------------------------------------------------------------------------
__global__ void __launch_bounds__(256) deform_sample_kernel(
    const float* __restrict__ ref,        // (B,L,LV,2)
    const float* __restrict__ off,        // rows x 256  (M,LV,P,2)
    const float* __restrict__ logits,     // rows x 128  (M,LV*P)
    const float* __restrict__ value,      // rows x 256  (M,DH)
    float* __restrict__ out)              // rows x 256
{
    const int row  = blockIdx.x;          // b*L + q
    const int b    = row / Lc;
    const int m    = threadIdx.x >> 5;    // head
    const int lane = threadIdx.x & 31;    // channel

    // per-head softmax over 16 logits (lanes 0..15 hold one each)
    const float* lg = logits + (size_t)row * 128 + m * 16;
    float e  = (lane < 16) ? lg[lane] : -3.4e38f;
    float mx = e;
    #pragma unroll
    for (int o = 16; o > 0; o >>= 1) mx = fmaxf(mx, __shfl_xor_sync(0xffffffffu, mx, o));
    float ex = (lane < 16) ? __expf(e - mx) : 0.f;
    float sm = ex;
    #pragma unroll
    for (int o = 16; o > 0; o >>= 1) sm += __shfl_xor_sync(0xffffffffu, sm, o);
    float w = ex / sm;

    const float* offr = off + (size_t)row * 256 + m * 32;  // (lv*4+p)*2
    const float* refr = ref + (size_t)row * 8;             // (lv,2)
    const float* valb = value + (size_t)b * Lc * 256;

    float acc = 0.f;
    #pragma unroll
    for (int s = 0; s < 16; s++) {
        const int lv = s >> 2;
        const int Wi = c_W[lv], Hi = c_H[lv], s0 = c_S0[lv];
        const float Wl = (float)Wi, Hl = (float)Hi;
        float lx = refr[lv * 2 + 0] + offr[s * 2 + 0] / Wl;
        float ly = refr[lv * 2 + 1] + offr[s * 2 + 1] / Hl;
        float x = lx * Wl - 0.5f;
        float y = ly * Hl - 0.5f;
        float x0f = floorf(x), y0f = floorf(y);
        float wx = x - x0f, wy = y - y0f;
        int x0 = (int)x0f, y0 = (int)y0f;
        float aw = __shfl_sync(0xffffffffu, w, s);
        #pragma unroll
        for (int c = 0; c < 4; c++) {
            int dy = c >> 1, dx = c & 1;
            int xi = x0 + dx, yi = y0 + dy;
            if (xi >= 0 && xi < Wi && yi >= 0 && yi < Hi) {
                float cw = (dy ? wy : 1.f - wy) * (dx ? wx : 1.f - wx);
                float v = valb[(size_t)(s0 + yi * Wi + xi) * 256 + m * 32 + lane];
                acc += aw * cw * v;
            }
        }
    }
    out[(size_t)row * 256 + m * 32 + lane] = acc;
}

// ---------------------------------------------------------------------------
// Fused residual add + LayerNorm over DM=256. 1 block per row, 256 threads.
// ---------------------------------------------------------------------------
__global__ void __launch_bounds__(256) add_ln_kernel(
    const float* __restrict__ x1, const float* __restrict__ x2,
    const float* __restrict__ g,  const float* __restrict__ bb,
    float* __restrict__ out)
{
    const int row = blockIdx.x;
    const int t   = threadIdx.x;
    __shared__ float red[8];

    float v = x1[(size_t)row * 256 + t] + x2[(size_t)row * 256 + t];

    float s = v;
    #pragma unroll
    for (int o = 16; o > 0; o >>= 1) s += __shfl_xor_sync(0xffffffffu, s, o);
    if ((t & 31) == 0) red[t >> 5] = s;
    __syncthreads();
    float tot = 0.f;
    #pragma unroll
    for (int i = 0; i < 8; i++) tot += red[i];
    const float mean = tot * (1.f / 256.f);
    __syncthreads();

    float d  = v - mean;
    float sq = d * d;
    #pragma unroll
    for (int o = 16; o > 0; o >>= 1) sq += __shfl_xor_sync(0xffffffffu, sq, o);
    if ((t & 31) == 0) red[t >> 5] = sq;
    __syncthreads();
    float vtot = 0.f;
    #pragma unroll
    for (int i = 0; i < 8; i++) vtot += red[i];
    const float var = vtot * (1.f / 256.f);

    out[(size_t)row * 256 + t] = d * rsqrtf(var + 1e-5f) * g[t] + bb[t];
}

// ---------------------------------------------------------------------------
// Launch
// ---------------------------------------------------------------------------
static float* sym_addr(const void* s) {
    void* p = nullptr;
    cudaGetSymbolAddress(&p, s);
    return (float*)p;
}

extern "C" void kernel_launch(void* const* d_in, const int* in_sizes, int n_in,
                              void* d_out, int out_size)
{
    const float* src     = (const float*)d_in[0];
    // d_in[1] = pos (unused by the reference forward)
    const float* refp    = (const float*)d_in[2];
    const float* q_pos   = (const float*)d_in[3];
    const float* q_feat  = (const float*)d_in[4];
    const float* W_off   = (const float*)d_in[5];
    const float* b_off   = (const float*)d_in[6];
    const float* W_attn  = (const float*)d_in[7];
    const float* b_attn  = (const float*)d_in[8];
    const float* W_v     = (const float*)d_in[9];
    const float* b_v     = (const float*)d_in[10];
    const float* W_outp  = (const float*)d_in[11];
    const float* b_outp  = (const float*)d_in[12];
    const float* ln1_g   = (const float*)d_in[13];
    const float* ln1_b   = (const float*)d_in[14];
    const float* W1      = (const float*)d_in[15];
    const float* b1      = (const float*)d_in[16];
    const float* W2      = (const float*)d_in[17];
    const float* b2      = (const float*)d_in[18];
    const float* ln2_g   = (const float*)d_in[19];
    const float* ln2_b   = (const float*)d_in[20];
    // d_in[21] = spatial_shapes, d_in[22] = level_start_index: compile-time
    // constants for this problem; hardcoded in c_H/c_W/c_S0.
    float* out = (float*)d_out;

    float* buf0  = sym_addr(g_buf0);
    float* buf1  = sym_addr(g_buf1);
    float* buf2  = sym_addr(g_buf2);
    float* logit = sym_addr(g_logit);
    float* f1    = sym_addr(g_ffn1);

    float* query = buf0;
    float* value = buf1;
    float* offb  = buf2;
    float* samp  = buf0;   // query dead after off/logit GEMMs
    float* attn  = buf2;   // off dead after sampling
    float* h     = buf1;   // value dead after sampling
    float* f2    = buf2;   // attn dead after add_ln

    const int GM = (ROWS + 127) / 128;   // 352

    add_kernel<<<ROWS, 256>>>(q_feat, q_pos, query);

    sgemm_bias<false><<<dim3(GM, 2), 256>>>(src, W_v, b_v, value, ROWS, 256, 256);
    sgemm_bias<false><<<dim3(GM, 2), 256>>>(query, W_off, b_off, offb, ROWS, 256, 256);
    sgemm_bias<false><<<dim3(GM, 1), 256>>>(query, W_attn, b_attn, logit, ROWS, 128, 256);

    deform_sample_kernel<<<ROWS, 256>>>(refp, offb, logit, value, samp);

    sgemm_bias<false><<<dim3(GM, 2), 256>>>(samp, W_outp, b_outp, attn, ROWS, 256, 256);

    add_ln_kernel<<<ROWS, 256>>>(q_feat, attn, ln1_g, ln1_b, h);

    sgemm_bias<true ><<<dim3(GM, 8), 256>>>(h,  W1, b1, f1, ROWS, 1024, 256);
    sgemm_bias<false><<<dim3(GM, 2), 256>>>(f1, W2, b2, f2, ROWS, 256, 1024);

    add_ln_kernel<<<ROWS, 256>>>(h, f2, ln2_g, ln2_b, out);
}

// round 6
// speedup vs baseline: 1.0026x; 1.0026x over previous
#include <cuda_runtime.h>
#include <cuda_bf16.h>
#include <cstdint>

// Problem constants (fixed by setup_inputs)
#define Bc   4
#define Lc   11253
#define ROWS (Bc * Lc)        // 45012
#define DMc  256
#define Mh   8
#define DHc  32
#define LVc  4
#define Pc   4
#define DFc  1024

// Hardcoded level geometry (SHAPES / level_start_index are problem constants;
// avoids depending on the harness's int64 materialization entirely).
__device__ __constant__ int c_H [4] = {92, 46, 23, 12};
__device__ __constant__ int c_W [4] = {92, 46, 23, 12};
__device__ __constant__ int c_S0[4] = {0, 8464, 10580, 11109};

// ---------------------------------------------------------------------------
// Scratch (allocation-free: __device__ globals), aliased across stages:
//   buf0: query -> samp ; buf1: value -> h ; buf2: off -> attn -> ffn2
// ---------------------------------------------------------------------------
__device__ float g_buf0 [ROWS * DMc];
__device__ float g_buf1 [ROWS * DMc];
__device__ float g_buf2 [ROWS * DMc];
__device__ float g_logit[ROWS * 128];
__device__ float g_ffn1 [ROWS * DFc];

// ---------------------------------------------------------------------------
// Elementwise add: query = q_feat + q_pos
// ---------------------------------------------------------------------------
__global__ void __launch_bounds__(256) add_kernel(
    const float* __restrict__ a, const float* __restrict__ b,
    float* __restrict__ o)
{
    size_t i = (size_t)blockIdx.x * 256 + threadIdx.x;
    o[i] = a[i] + b[i];
}

// ---------------------------------------------------------------------------
// SGEMM: C[Mr,N] = A[Mr,K] @ B[K,N] + bias (optional ReLU)
// BM=BN=128, BK=8, 256 threads, 8x8 per thread in 2x2 quadrants of 4x4.
// ---------------------------------------------------------------------------
template<bool RELU>
__global__ void __launch_bounds__(256) sgemm_bias(
    const float* __restrict__ A, const float* __restrict__ Bm,
    const float* __restrict__ bias, float* __restrict__ C,
    int Mr, int N, int K)
{
    __shared__ float As[8][128];
    __shared__ float Bs[8][128];

    const int tid  = threadIdx.x;
    const int row0 = blockIdx.x * 128;
    const int col0 = blockIdx.y * 128;

    const int tr = (tid >> 4) * 4;
    const int tc = (tid & 15) * 4;

    float acc[2][2][4][4];
    #pragma unroll
    for (int qi = 0; qi < 2; qi++)
        #pragma unroll
        for (int qj = 0; qj < 2; qj++)
            #pragma unroll
            for (int i = 0; i < 4; i++)
                #pragma unroll
                for (int j = 0; j < 4; j++)
                    acc[qi][qj][i][j] = 0.f;

    const int aRow = tid >> 1;
    const int aK   = (tid & 1) * 4;
    const int bRow = tid >> 5;
    const int bCol = (tid & 31) * 4;

    const bool aValid = (row0 + aRow) < Mr;
    const float* Aptr = A + (size_t)(row0 + aRow) * K + aK;
    const float* Bptr = Bm + (size_t)bRow * N + col0 + bCol;

    for (int k0 = 0; k0 < K; k0 += 8) {
        float4 av = aValid ? *(const float4*)(Aptr + k0)
                           : make_float4(0.f, 0.f, 0.f, 0.f);
        As[aK + 0][aRow] = av.x;
        As[aK + 1][aRow] = av.y;
        As[aK + 2][aRow] = av.z;
        As[aK + 3][aRow] = av.w;
        *(float4*)&Bs[bRow][bCol] = *(const float4*)(Bptr + (size_t)k0 * N);
        __syncthreads();

        #pragma unroll
        for (int kk = 0; kk < 8; kk++) {
            float4 a0 = *(const float4*)&As[kk][tr];
            float4 a1 = *(const float4*)&As[kk][tr + 64];
            float4 b0 = *(const float4*)&Bs[kk][tc];
            float4 b1 = *(const float4*)&Bs[kk][tc + 64];
            float ar[2][4] = {{a0.x, a0.y, a0.z, a0.w}, {a1.x, a1.y, a1.z, a1.w}};
            float br[2][4] = {{b0.x, b0.y, b0.z, b0.w}, {b1.x, b1.y, b1.z, b1.w}};
            #pragma unroll
            for (int qi = 0; qi < 2; qi++)
                #pragma unroll
                for (int qj = 0; qj < 2; qj++)
                    #pragma unroll
                    for (int i = 0; i < 4; i++)
                        #pragma unroll
                        for (int j = 0; j < 4; j++)
                            acc[qi][qj][i][j] += ar[qi][i] * br[qj][j];
        }
        __syncthreads();
    }

    #pragma unroll
    for (int qi = 0; qi < 2; qi++) {
        #pragma unroll
        for (int i = 0; i < 4; i++) {
            int gr = row0 + tr + qi * 64 + i;
            if (gr >= Mr) continue;
            #pragma unroll
            for (int qj = 0; qj < 2; qj++) {
                int gc = col0 + tc + qj * 64;
                float4 bv = *(const float4*)&bias[gc];
                float4 o;
                o.x = acc[qi][qj][i][0] + bv.x;
                o.y = acc[qi][qj][i][1] + bv.y;
                o.z = acc[qi][qj][i][2] + bv.z;
                o.w = acc[qi][qj][i][3] + bv.w;
                if (RELU) {
                    o.x = fmaxf(o.x, 0.f); o.y = fmaxf(o.y, 0.f);
                    o.z = fmaxf(o.z, 0.f); o.w = fmaxf(o.w, 0.f);
                }
                *(float4*)&C[(size_t)gr * N + gc] = o;
            }
        }
    }
}

// ---------------------------------------------------------------------------
// Deformable sampling: 1 block per query row, 1 warp per head, lane = channel.
// Softmax over LV*P=16 logits per head, then bilinear gather-accumulate.
// Level geometry is compile-time constant (c_H/c_W/c_S0).
// ---------------------------------------------------------------------------
__global__ void __launch_bounds__(256) deform_sample_kernel(
    const float* __restrict__ ref,        // (B,L,LV,2)
    const float* __restrict__ off,        // rows x 256  (M,LV,P,2)
    const float* __restrict__ logits,     // rows x 128  (M,LV*P)
    const float* __restrict__ value,      // rows x 256  (M,DH)
    float* __restrict__ out)              // rows x 256
{
    const int row  = blockIdx.x;          // b*L + q
    const int b    = row / Lc;
    const int m    = threadIdx.x >> 5;    // head
    const int lane = threadIdx.x & 31;    // channel

    // per-head softmax over 16 logits (lanes 0..15 hold one each)
    const float* lg = logits + (size_t)row * 128 + m * 16;
    float e  = (lane < 16) ? lg[lane] : -3.4e38f;
    float mx = e;
    #pragma unroll
    for (int o = 16; o > 0; o >>= 1) mx = fmaxf(mx, __shfl_xor_sync(0xffffffffu, mx, o));
    float ex = (lane < 16) ? __expf(e - mx) : 0.f;
    float sm = ex;
    #pragma unroll
    for (int o = 16; o > 0; o >>= 1) sm += __shfl_xor_sync(0xffffffffu, sm, o);
    float w = ex / sm;

    const float* offr = off + (size_t)row * 256 + m * 32;  // (lv*4+p)*2
    const float* refr = ref + (size_t)row * 8;             // (lv,2)
    const float* valb = value + (size_t)b * Lc * 256;

    float acc = 0.f;
    #pragma unroll
    for (int s = 0; s < 16; s++) {
        const int lv = s >> 2;
        const int Wi = c_W[lv], Hi = c_H[lv], s0 = c_S0[lv];
        const float Wl = (float)Wi, Hl = (float)Hi;
        float lx = refr[lv * 2 + 0] + offr[s * 2 + 0] / Wl;
        float ly = refr[lv * 2 + 1] + offr[s * 2 + 1] / Hl;
        float x = lx * Wl - 0.5f;
        float y = ly * Hl - 0.5f;
        float x0f = floorf(x), y0f = floorf(y);
        float wx = x - x0f, wy = y - y0f;
        int x0 = (int)x0f, y0 = (int)y0f;
        float aw = __shfl_sync(0xffffffffu, w, s);
        #pragma unroll
        for (int c = 0; c < 4; c++) {
            int dy = c >> 1, dx = c & 1;
            int xi = x0 + dx, yi = y0 + dy;
            if (xi >= 0 && xi < Wi && yi >= 0 && yi < Hi) {
                float cw = (dy ? wy : 1.f - wy) * (dx ? wx : 1.f - wx);
                float v = valb[(size_t)(s0 + yi * Wi + xi) * 256 + m * 32 + lane];
                acc += aw * cw * v;
            }
        }
    }
    out[(size_t)row * 256 + m * 32 + lane] = acc;
}

// ---------------------------------------------------------------------------
// Fused residual add + LayerNorm over DM=256. 1 block per row, 256 threads.
// ---------------------------------------------------------------------------
__global__ void __launch_bounds__(256) add_ln_kernel(
    const float* __restrict__ x1, const float* __restrict__ x2,
    const float* __restrict__ g,  const float* __restrict__ bb,
    float* __restrict__ out)
{
    const int row = blockIdx.x;
    const int t   = threadIdx.x;
    __shared__ float red[8];

    float v = x1[(size_t)row * 256 + t] + x2[(size_t)row * 256 + t];

    float s = v;
    #pragma unroll
    for (int o = 16; o > 0; o >>= 1) s += __shfl_xor_sync(0xffffffffu, s, o);
    if ((t & 31) == 0) red[t >> 5] = s;
    __syncthreads();
    float tot = 0.f;
    #pragma unroll
    for (int i = 0; i < 8; i++) tot += red[i];
    const float mean = tot * (1.f / 256.f);
    __syncthreads();

    float d  = v - mean;
    float sq = d * d;
    #pragma unroll
    for (int o = 16; o > 0; o >>= 1) sq += __shfl_xor_sync(0xffffffffu, sq, o);
    if ((t & 31) == 0) red[t >> 5] = sq;
    __syncthreads();
    float vtot = 0.f;
    #pragma unroll
    for (int i = 0; i < 8; i++) vtot += red[i];
    const float var = vtot * (1.f / 256.f);

    out[(size_t)row * 256 + t] = d * rsqrtf(var + 1e-5f) * g[t] + bb[t];
}

// ---------------------------------------------------------------------------
// Launch
// ---------------------------------------------------------------------------
static float* sym_addr(const void* s) {
    void* p = nullptr;
    cudaGetSymbolAddress(&p, s);
    return (float*)p;
}

extern "C" void kernel_launch(void* const* d_in, const int* in_sizes, int n_in,
                              void* d_out, int out_size)
{
    const float* src     = (const float*)d_in[0];
    // d_in[1] = pos (unused by the reference forward)
    const float* refp    = (const float*)d_in[2];
    const float* q_pos   = (const float*)d_in[3];
    const float* q_feat  = (const float*)d_in[4];
    const float* W_off   = (const float*)d_in[5];
    const float* b_off   = (const float*)d_in[6];
    const float* W_attn  = (const float*)d_in[7];
    const float* b_attn  = (const float*)d_in[8];
    const float* W_v     = (const float*)d_in[9];
    const float* b_v     = (const float*)d_in[10];
    const float* W_outp  = (const float*)d_in[11];
    const float* b_outp  = (const float*)d_in[12];
    const float* ln1_g   = (const float*)d_in[13];
    const float* ln1_b   = (const float*)d_in[14];
    const float* W1      = (const float*)d_in[15];
    const float* b1      = (const float*)d_in[16];
    const float* W2      = (const float*)d_in[17];
    const float* b2      = (const float*)d_in[18];
    const float* ln2_g   = (const float*)d_in[19];
    const float* ln2_b   = (const float*)d_in[20];
    // d_in[21] = spatial_shapes, d_in[22] = level_start_index: compile-time
    // constants for this problem; hardcoded in c_H/c_W/c_S0.
    float* out = (float*)d_out;

    float* buf0  = sym_addr(g_buf0);
    float* buf1  = sym_addr(g_buf1);
    float* buf2  = sym_addr(g_buf2);
    float* logit = sym_addr(g_logit);
    float* f1    = sym_addr(g_ffn1);

    float* query = buf0;
    float* value = buf1;
    float* offb  = buf2;
    float* samp  = buf0;   // query dead after off/logit GEMMs
    float* attn  = buf2;   // off dead after sampling
    float* h     = buf1;   // value dead after sampling
    float* f2    = buf2;   // attn dead after add_ln

    const int GM = (ROWS + 127) / 128;   // 352

    add_kernel<<<ROWS, 256>>>(q_feat, q_pos, query);

    sgemm_bias<false><<<dim3(GM, 2), 256>>>(src, W_v, b_v, value, ROWS, 256, 256);
    sgemm_bias<false><<<dim3(GM, 2), 256>>>(query, W_off, b_off, offb, ROWS, 256, 256);
    sgemm_bias<false><<<dim3(GM, 1), 256>>>(query, W_attn, b_attn, logit, ROWS, 128, 256);

    deform_sample_kernel<<<ROWS, 256>>>(refp, offb, logit, value, samp);

    sgemm_bias<false><<<dim3(GM, 2), 256>>>(samp, W_outp, b_outp, attn, ROWS, 256, 256);

    add_ln_kernel<<<ROWS, 256>>>(q_feat, attn, ln1_g, ln1_b, h);

    sgemm_bias<true ><<<dim3(GM, 8), 256>>>(h,  W1, b1, f1, ROWS, 1024, 256);
    sgemm_bias<false><<<dim3(GM, 2), 256>>>(f1, W2, b2, f2, ROWS, 256, 1024);

    add_ln_kernel<<<ROWS, 256>>>(h, f2, ln2_g, ln2_b, out);
}